// round 1
// baseline (speedup 1.0000x reference)
#include <cuda_runtime.h>
#include <math.h>

#define NB 4
#define NT 4096
#define ND 1024
#define NH 64

// Scratch for Q, K, V projections (4 MB each)
__device__ float g_Q[NB * NT * NH];
__device__ float g_K[NB * NT * NH];
__device__ float g_V[NB * NT * NH];

// XOR swizzle for 64-wide smem rows: conflict-free column access, no padding.
#define SWZ(r, c) (((r) << 6) + (((c) ^ ((r) & 31))))

// ---------------------------------------------------------------------------
// Kernel 1: fused QKV projection.
// out[row, c] = sum_k x[row, k] * w[c, k]  for w in {wq, wk, wv}
// Grid: 16384/64 = 256 blocks. Block: 256 threads.
// Per-CTA tile: 64 rows x 192 cols (3 matrices x 64). Thread tile 4x12.
// ---------------------------------------------------------------------------
__global__ __launch_bounds__(256) void qkv_kernel(
    const float* __restrict__ x,
    const float* __restrict__ wq,
    const float* __restrict__ wk,
    const float* __restrict__ wv)
{
    __shared__ float sm[256][33];  // rows 0-63: x tile; 64-255: wq/wk/wv tiles
    const int row0 = blockIdx.x * 64;
    const int tid = threadIdx.x;
    const int tx = tid & 15;   // 16 col groups
    const int ty = tid >> 4;   // 16 row groups (4 rows each)

    // Cooperative-load source pointers: 256 logical rows, 1 per thread slot,
    // each thread loads 8 rows (one float4 of 32-k chunk per row).
    const float* srcs[8];
#pragma unroll
    for (int i = 0; i < 8; i++) {
        int r = (tid >> 3) + i * 32;
        const float* p;
        if (r < 64)       p = x  + (size_t)(row0 + r) * ND;
        else if (r < 128) p = wq + (size_t)(r - 64) * ND;
        else if (r < 192) p = wk + (size_t)(r - 128) * ND;
        else              p = wv + (size_t)(r - 192) * ND;
        srcs[i] = p + (tid & 7) * 4;
    }

    float acc[4][12];
#pragma unroll
    for (int i = 0; i < 4; i++)
#pragma unroll
        for (int j = 0; j < 12; j++) acc[i][j] = 0.0f;

    for (int k0 = 0; k0 < ND; k0 += 32) {
        __syncthreads();  // previous iteration's compute done
#pragma unroll
        for (int i = 0; i < 8; i++) {
            int r = (tid >> 3) + i * 32;
            int kk = (tid & 7) * 4;
            float4 v = *(const float4*)(srcs[i] + k0);
            sm[r][kk + 0] = v.x; sm[r][kk + 1] = v.y;
            sm[r][kk + 2] = v.z; sm[r][kk + 3] = v.w;
        }
        __syncthreads();
#pragma unroll 8
        for (int k = 0; k < 32; k++) {
            float xa[4];
#pragma unroll
            for (int i = 0; i < 4; i++) xa[i] = sm[ty * 4 + i][k];
            float wb[12];
#pragma unroll
            for (int mm = 0; mm < 3; mm++)
#pragma unroll
                for (int j = 0; j < 4; j++)
                    wb[mm * 4 + j] = sm[64 + mm * 64 + tx * 4 + j][k];
#pragma unroll
            for (int i = 0; i < 4; i++)
#pragma unroll
                for (int j = 0; j < 12; j++)
                    acc[i][j] = fmaf(xa[i], wb[j], acc[i][j]);
        }
    }

    float* outs[3] = {g_Q, g_K, g_V};
#pragma unroll
    for (int mm = 0; mm < 3; mm++)
#pragma unroll
        for (int i = 0; i < 4; i++) {
            float4 v = make_float4(acc[i][mm * 4 + 0], acc[i][mm * 4 + 1],
                                   acc[i][mm * 4 + 2], acc[i][mm * 4 + 3]);
            *(float4*)(outs[mm] + (size_t)(row0 + ty * 4 + i) * NH + tx * 4) = v;
        }
}

// ---------------------------------------------------------------------------
// Kernel 2: flash attention, BLOCK_M = BLOCK_N = 64, head dim 64.
// Grid: (T/64 = 64, B = 4). Block: 256 threads, thread tile 4x4.
// smem: Q tile + (K|P shared buffer) + V tile = exactly 48 KB (XOR swizzled).
// ---------------------------------------------------------------------------
__global__ __launch_bounds__(256) void attn_kernel(float* __restrict__ out)
{
    __shared__ float qs[64 * 64];
    __shared__ float kps[64 * 64];  // K tile, then reused for P tile
    __shared__ float vs[64 * 64];

    const int b  = blockIdx.y;
    const int q0 = blockIdx.x * 64;
    const float* Qp = g_Q + ((size_t)b * NT + q0) * NH;
    const float* Kp = g_K + (size_t)b * NT * NH;
    const float* Vp = g_V + (size_t)b * NT * NH;

    const int tid = threadIdx.x;
    const int tx = tid & 15;   // col group (4 cols)
    const int ty = tid >> 4;   // row group (4 rows)

    // Load Q tile once
#pragma unroll
    for (int i = 0; i < 4; i++) {
        int r  = (tid >> 4) + i * 16;
        int kk = (tid & 15) * 4;
        float4 v = *(const float4*)(Qp + r * NH + kk);
        qs[SWZ(r, kk + 0)] = v.x; qs[SWZ(r, kk + 1)] = v.y;
        qs[SWZ(r, kk + 2)] = v.z; qs[SWZ(r, kk + 3)] = v.w;
    }

    float o[4][4];
    float m[4], l[4];
#pragma unroll
    for (int i = 0; i < 4; i++) {
        m[i] = -1e30f; l[i] = 0.0f;
#pragma unroll
        for (int j = 0; j < 4; j++) o[i][j] = 0.0f;
    }

    const float scale = 0.125f;  // 1/sqrt(64)

    for (int kt = 0; kt < NT; kt += 64) {
        __syncthreads();  // prior GEMM2 done; also covers initial Q-load visibility
        // Load K and V tiles (64 keys x 64 dims each)
#pragma unroll
        for (int i = 0; i < 4; i++) {
            int r  = (tid >> 4) + i * 16;
            int kk = (tid & 15) * 4;
            float4 kv = *(const float4*)(Kp + (size_t)(kt + r) * NH + kk);
            kps[SWZ(r, kk + 0)] = kv.x; kps[SWZ(r, kk + 1)] = kv.y;
            kps[SWZ(r, kk + 2)] = kv.z; kps[SWZ(r, kk + 3)] = kv.w;
            float4 vv = *(const float4*)(Vp + (size_t)(kt + r) * NH + kk);
            vs[SWZ(r, kk + 0)] = vv.x; vs[SWZ(r, kk + 1)] = vv.y;
            vs[SWZ(r, kk + 2)] = vv.z; vs[SWZ(r, kk + 3)] = vv.w;
        }
        __syncthreads();

        // GEMM1: S = Q @ K^T  (64x64 tile, thread 4x4)
        float s[4][4];
#pragma unroll
        for (int i = 0; i < 4; i++)
#pragma unroll
            for (int j = 0; j < 4; j++) s[i][j] = 0.0f;
#pragma unroll 16
        for (int k = 0; k < 64; k++) {
            float qa[4], kb[4];
#pragma unroll
            for (int i = 0; i < 4; i++) qa[i] = qs[SWZ(ty * 4 + i, k)];
#pragma unroll
            for (int j = 0; j < 4; j++) kb[j] = kps[SWZ(tx * 4 + j, k)];
#pragma unroll
            for (int i = 0; i < 4; i++)
#pragma unroll
                for (int j = 0; j < 4; j++)
                    s[i][j] = fmaf(qa[i], kb[j], s[i][j]);
        }

        // Online softmax update (rows owned by 16 threads -> half-warp shuffles)
#pragma unroll
        for (int i = 0; i < 4; i++) {
            float mx = s[i][0];
#pragma unroll
            for (int j = 1; j < 4; j++) mx = fmaxf(mx, s[i][j]);
            mx *= scale;  // scale once; scale s below too
            mx = fmaxf(mx, __shfl_xor_sync(0xffffffffu, mx, 1));
            mx = fmaxf(mx, __shfl_xor_sync(0xffffffffu, mx, 2));
            mx = fmaxf(mx, __shfl_xor_sync(0xffffffffu, mx, 4));
            mx = fmaxf(mx, __shfl_xor_sync(0xffffffffu, mx, 8));
            float mnew = fmaxf(m[i], mx);
            float corr = __expf(m[i] - mnew);
            float rsum = 0.0f;
#pragma unroll
            for (int j = 0; j < 4; j++) {
                float p = __expf(fmaf(s[i][j], scale, -mnew));
                s[i][j] = p;
                rsum += p;
            }
            rsum += __shfl_xor_sync(0xffffffffu, rsum, 1);
            rsum += __shfl_xor_sync(0xffffffffu, rsum, 2);
            rsum += __shfl_xor_sync(0xffffffffu, rsum, 4);
            rsum += __shfl_xor_sync(0xffffffffu, rsum, 8);
            l[i] = l[i] * corr + rsum;
            m[i] = mnew;
#pragma unroll
            for (int j = 0; j < 4; j++) o[i][j] *= corr;
        }

        __syncthreads();  // all GEMM1 reads of kps done -> safe to overwrite with P
#pragma unroll
        for (int i = 0; i < 4; i++)
#pragma unroll
            for (int j = 0; j < 4; j++)
                kps[SWZ(ty * 4 + i, tx * 4 + j)] = s[i][j];
        __syncthreads();

        // GEMM2: O += P @ V  (thread 4x4)
#pragma unroll 16
        for (int ss = 0; ss < 64; ss++) {
            float pa[4], vb[4];
#pragma unroll
            for (int i = 0; i < 4; i++) pa[i] = kps[SWZ(ty * 4 + i, ss)];
#pragma unroll
            for (int j = 0; j < 4; j++) vb[j] = vs[SWZ(ss, tx * 4 + j)];
#pragma unroll
            for (int i = 0; i < 4; i++)
#pragma unroll
                for (int j = 0; j < 4; j++)
                    o[i][j] = fmaf(pa[i], vb[j], o[i][j]);
        }
    }

    // Epilogue: normalize and store
#pragma unroll
    for (int i = 0; i < 4; i++) {
        float inv = 1.0f / l[i];
        float4 v = make_float4(o[i][0] * inv, o[i][1] * inv,
                               o[i][2] * inv, o[i][3] * inv);
        *(float4*)(out + ((size_t)b * NT + q0 + ty * 4 + i) * NH + tx * 4) = v;
    }
}

// ---------------------------------------------------------------------------
extern "C" void kernel_launch(void* const* d_in, const int* in_sizes, int n_in,
                              void* d_out, int out_size)
{
    const float* x  = (const float*)d_in[0];
    const float* wq = (const float*)d_in[1];
    const float* wk = (const float*)d_in[2];
    const float* wv = (const float*)d_in[3];
    float* out = (float*)d_out;

    (void)in_sizes; (void)n_in; (void)out_size;

    qkv_kernel<<<(NB * NT) / 64, 256>>>(x, wq, wk, wv);
    attn_kernel<<<dim3(NT / 64, NB), 256>>>(out);
}

// round 2
// speedup vs baseline: 4.3526x; 4.3526x over previous
#include <cuda_runtime.h>
#include <math.h>
#include <stdint.h>

#define NB 4
#define NT 4096
#define ND 1024
#define NH 64
#define SPLIT 2

// Scratch: tf32-rounded Q (pre-scaled by 1/8), K, V; split partials.
__device__ float g_Q[NB * NT * NH];
__device__ float g_K[NB * NT * NH];
__device__ float g_V[NB * NT * NH];
__device__ float g_Op[SPLIT][NB * NT * NH];
__device__ float g_ml[SPLIT][NB * NT][2];

// Round fp32 -> tf32 bit pattern (round-to-nearest: unbiased over long dots).
__device__ __forceinline__ uint32_t f2tf(float f) {
    uint32_t u;
    asm("cvt.rna.tf32.f32 %0, %1;" : "=r"(u) : "f"(f));
    return u;
}

// D += A*B, m16n8k8 tf32.
__device__ __forceinline__ void mma8(float d[4],
                                     uint32_t a0, uint32_t a1, uint32_t a2, uint32_t a3,
                                     uint32_t b0, uint32_t b1) {
    asm volatile(
        "mma.sync.aligned.m16n8k8.row.col.f32.tf32.tf32.f32 "
        "{%0,%1,%2,%3}, {%4,%5,%6,%7}, {%8,%9}, {%0,%1,%2,%3};"
        : "+f"(d[0]), "+f"(d[1]), "+f"(d[2]), "+f"(d[3])
        : "r"(a0), "r"(a1), "r"(a2), "r"(a3), "r"(b0), "r"(b1));
}

// float4-granular XOR swizzle on 64-float rows: conflict-free fragment access,
// zero padding (3 x 16KB = 48KB static smem exactly).
#define SW(r, c) (((r) << 6) + ((((c) >> 2) ^ ((r) & 7)) << 2) + ((c) & 3))

// ---------------------------------------------------------------------------
// Kernel 1: fused QKV projection with tf32 mma.
// Block: 64 rows x 192 cols (Q|K|V), 8 warps (4 row-tiles x 2 col-halves).
// ---------------------------------------------------------------------------
#define PW 36  // smem pitch for 32-wide k-chunks (4-way bank spread)

__global__ __launch_bounds__(256) void qkv_kernel(
    const float* __restrict__ x,
    const float* __restrict__ wq,
    const float* __restrict__ wk,
    const float* __restrict__ wv)
{
    __shared__ float sm[256 * PW];  // rows 0-63: x | 64-127: wq | 128-191: wk | 192-255: wv
    const int t = threadIdx.x;
    const int row0 = blockIdx.x * 64;
    const int w = t >> 5, lane = t & 31, g = lane >> 2, t4 = lane & 3;
    const int wr = w & 3, wc = w >> 2;

    const float* srcs[8];
#pragma unroll
    for (int i = 0; i < 8; i++) {
        int r = (t >> 3) + 32 * i;
        const float* p;
        if (r < 64)       p = x  + (size_t)(row0 + r) * ND;
        else if (r < 128) p = wq + (size_t)(r - 64) * ND;
        else if (r < 192) p = wk + (size_t)(r - 128) * ND;
        else              p = wv + (size_t)(r - 192) * ND;
        srcs[i] = p + (t & 7) * 4;
    }

    float acc[12][4];
#pragma unroll
    for (int nt = 0; nt < 12; nt++)
#pragma unroll
        for (int j = 0; j < 4; j++) acc[nt][j] = 0.0f;

    for (int k0 = 0; k0 < ND; k0 += 32) {
        __syncthreads();
#pragma unroll
        for (int i = 0; i < 8; i++) {
            int r = (t >> 3) + 32 * i;
            float4 v = *(const float4*)(srcs[i] + k0);
            float* d = &sm[r * PW + (t & 7) * 4];
            d[0] = __uint_as_float(f2tf(v.x));
            d[1] = __uint_as_float(f2tf(v.y));
            d[2] = __uint_as_float(f2tf(v.z));
            d[3] = __uint_as_float(f2tf(v.w));
        }
        __syncthreads();
#pragma unroll
        for (int ks8 = 0; ks8 < 4; ks8++) {
            int kk = ks8 * 8;
            uint32_t a0 = __float_as_uint(sm[(16 * wr + g) * PW + kk + t4]);
            uint32_t a1 = __float_as_uint(sm[(16 * wr + g + 8) * PW + kk + t4]);
            uint32_t a2 = __float_as_uint(sm[(16 * wr + g) * PW + kk + t4 + 4]);
            uint32_t a3 = __float_as_uint(sm[(16 * wr + g + 8) * PW + kk + t4 + 4]);
#pragma unroll
            for (int nt = 0; nt < 12; nt++) {
                int br = 64 + 96 * wc + 8 * nt + g;
                uint32_t b0 = __float_as_uint(sm[br * PW + kk + t4]);
                uint32_t b1 = __float_as_uint(sm[br * PW + kk + t4 + 4]);
                mma8(acc[nt], a0, a1, a2, a3, b0, b1);
            }
        }
    }

    // Epilogue: route to Q/K/V, scale Q by 1/sqrt(64), round to tf32.
#pragma unroll
    for (int nt = 0; nt < 12; nt++) {
        int gc = 96 * wc + 8 * nt + 2 * t4;
        int mm = gc >> 6;
        int h = gc & 63;
        float* dst = (mm == 0) ? g_Q : (mm == 1) ? g_K : g_V;
        float sc = (mm == 0) ? 0.125f : 1.0f;
        int r1 = row0 + 16 * wr + g;
        dst[(size_t)r1 * NH + h]           = __uint_as_float(f2tf(acc[nt][0] * sc));
        dst[(size_t)r1 * NH + h + 1]       = __uint_as_float(f2tf(acc[nt][1] * sc));
        dst[(size_t)(r1 + 8) * NH + h]     = __uint_as_float(f2tf(acc[nt][2] * sc));
        dst[(size_t)(r1 + 8) * NH + h + 1] = __uint_as_float(f2tf(acc[nt][3] * sc));
    }
}

// ---------------------------------------------------------------------------
// Kernel 2: flash attention, tf32 mma. BLOCK_M=64, BLOCK_N=64, 4 warps.
// Each warp owns 16 q-rows x all 64 cols -> softmax row stats are intra-quad.
// Split-KV over blockIdx.z; partials (numerator O, m, l) to scratch.
// ---------------------------------------------------------------------------
__global__ __launch_bounds__(128) void attn_kernel()
{
    __shared__ float qs[64 * 64];
    __shared__ float ks[64 * 64];  // K tile, then reused as P tile
    __shared__ float vs[64 * 64];

    const int b = blockIdx.y, q0 = blockIdx.x * 64, sp = blockIdx.z;
    const int t = threadIdx.x, w = t >> 5, lane = t & 31;
    const int g = lane >> 2, t4 = lane & 3;
    const int r0 = w * 16;

    const float* Qp = g_Q + ((size_t)b * NT + q0) * NH;
    const float* Kp = g_K + (size_t)b * NT * NH;
    const float* Vp = g_V + (size_t)b * NT * NH;

    // Load Q tile (already scaled + tf32-rounded)
#pragma unroll
    for (int i = 0; i < 8; i++) {
        int r = (t >> 4) + 8 * i;
        int c = (t & 15) * 4;
        *(float4*)&qs[SW(r, c)] = *(const float4*)(Qp + r * NH + c);
    }

    float s[8][4], o[8][4];
    float m[2] = {-1e30f, -1e30f}, l[2] = {0.0f, 0.0f};
#pragma unroll
    for (int nt = 0; nt < 8; nt++)
#pragma unroll
        for (int j = 0; j < 4; j++) o[nt][j] = 0.0f;

    const int kt_beg = sp * (NT / SPLIT);
    const int kt_end = kt_beg + (NT / SPLIT);

    for (int kt = kt_beg; kt < kt_end; kt += 64) {
        __syncthreads();  // prior GEMM2 reads of ks/vs complete
#pragma unroll
        for (int i = 0; i < 8; i++) {
            int r = (t >> 4) + 8 * i;
            int c = (t & 15) * 4;
            *(float4*)&ks[SW(r, c)] = *(const float4*)(Kp + (size_t)(kt + r) * NH + c);
            *(float4*)&vs[SW(r, c)] = *(const float4*)(Vp + (size_t)(kt + r) * NH + c);
        }
        __syncthreads();

        // GEMM1: S = Q @ K^T (already includes 1/sqrt(hd) via Q scaling)
#pragma unroll
        for (int nt = 0; nt < 8; nt++) {
            s[nt][0] = s[nt][1] = s[nt][2] = s[nt][3] = 0.0f;
        }
#pragma unroll
        for (int kk8 = 0; kk8 < 8; kk8++) {
            int k0 = kk8 * 8;
            uint32_t a0 = __float_as_uint(qs[SW(r0 + g, k0 + t4)]);
            uint32_t a1 = __float_as_uint(qs[SW(r0 + g + 8, k0 + t4)]);
            uint32_t a2 = __float_as_uint(qs[SW(r0 + g, k0 + t4 + 4)]);
            uint32_t a3 = __float_as_uint(qs[SW(r0 + g + 8, k0 + t4 + 4)]);
#pragma unroll
            for (int nt = 0; nt < 8; nt++) {
                uint32_t b0 = __float_as_uint(ks[SW(nt * 8 + g, k0 + t4)]);
                uint32_t b1 = __float_as_uint(ks[SW(nt * 8 + g, k0 + t4 + 4)]);
                mma8(s[nt], a0, a1, a2, a3, b0, b1);
            }
        }

        // Online softmax (rows g, g+8 of this warp; stats across quad via shfl)
        float mx0 = -1e30f, mx1 = -1e30f;
#pragma unroll
        for (int nt = 0; nt < 8; nt++) {
            mx0 = fmaxf(mx0, fmaxf(s[nt][0], s[nt][1]));
            mx1 = fmaxf(mx1, fmaxf(s[nt][2], s[nt][3]));
        }
        mx0 = fmaxf(mx0, __shfl_xor_sync(0xffffffffu, mx0, 1));
        mx0 = fmaxf(mx0, __shfl_xor_sync(0xffffffffu, mx0, 2));
        mx1 = fmaxf(mx1, __shfl_xor_sync(0xffffffffu, mx1, 1));
        mx1 = fmaxf(mx1, __shfl_xor_sync(0xffffffffu, mx1, 2));
        float mn0 = fmaxf(m[0], mx0), mn1 = fmaxf(m[1], mx1);
        float c0 = __expf(m[0] - mn0), c1 = __expf(m[1] - mn1);
        float sum0 = 0.0f, sum1 = 0.0f;
#pragma unroll
        for (int nt = 0; nt < 8; nt++) {
            s[nt][0] = __expf(s[nt][0] - mn0);
            s[nt][1] = __expf(s[nt][1] - mn0);
            s[nt][2] = __expf(s[nt][2] - mn1);
            s[nt][3] = __expf(s[nt][3] - mn1);
            sum0 += s[nt][0] + s[nt][1];
            sum1 += s[nt][2] + s[nt][3];
            o[nt][0] *= c0; o[nt][1] *= c0;
            o[nt][2] *= c1; o[nt][3] *= c1;
        }
        sum0 += __shfl_xor_sync(0xffffffffu, sum0, 1);
        sum0 += __shfl_xor_sync(0xffffffffu, sum0, 2);
        sum1 += __shfl_xor_sync(0xffffffffu, sum1, 1);
        sum1 += __shfl_xor_sync(0xffffffffu, sum1, 2);
        l[0] = l[0] * c0 + sum0;
        l[1] = l[1] * c1 + sum1;
        m[0] = mn0;
        m[1] = mn1;

        __syncthreads();  // all warps done reading ks (K) -> reuse as P
#pragma unroll
        for (int nt = 0; nt < 8; nt++) {
            int c = nt * 8 + 2 * t4;
            ks[SW(r0 + g, c)]         = __uint_as_float(f2tf(s[nt][0]));
            ks[SW(r0 + g, c + 1)]     = __uint_as_float(f2tf(s[nt][1]));
            ks[SW(r0 + g + 8, c)]     = __uint_as_float(f2tf(s[nt][2]));
            ks[SW(r0 + g + 8, c + 1)] = __uint_as_float(f2tf(s[nt][3]));
        }
        __syncthreads();

        // GEMM2: O += P @ V
#pragma unroll
        for (int kk8 = 0; kk8 < 8; kk8++) {
            int k0 = kk8 * 8;
            uint32_t a0 = __float_as_uint(ks[SW(r0 + g, k0 + t4)]);
            uint32_t a1 = __float_as_uint(ks[SW(r0 + g + 8, k0 + t4)]);
            uint32_t a2 = __float_as_uint(ks[SW(r0 + g, k0 + t4 + 4)]);
            uint32_t a3 = __float_as_uint(ks[SW(r0 + g + 8, k0 + t4 + 4)]);
#pragma unroll
            for (int nt = 0; nt < 8; nt++) {
                uint32_t b0 = __float_as_uint(vs[SW(k0 + t4, nt * 8 + g)]);
                uint32_t b1 = __float_as_uint(vs[SW(k0 + t4 + 4, nt * 8 + g)]);
                mma8(o[nt], a0, a1, a2, a3, b0, b1);
            }
        }
    }

    // Epilogue: write unnormalized numerator + (m, l) for this split
    float* Op = g_Op[sp] + ((size_t)b * NT + q0) * NH;
#pragma unroll
    for (int nt = 0; nt < 8; nt++) {
        int c = nt * 8 + 2 * t4;
        *(float2*)&Op[(size_t)(r0 + g) * NH + c]     = make_float2(o[nt][0], o[nt][1]);
        *(float2*)&Op[(size_t)(r0 + g + 8) * NH + c] = make_float2(o[nt][2], o[nt][3]);
    }
    if (t4 == 0) {
        int rr = b * NT + q0;
        g_ml[sp][rr + r0 + g][0] = m[0];
        g_ml[sp][rr + r0 + g][1] = l[0];
        g_ml[sp][rr + r0 + g + 8][0] = m[1];
        g_ml[sp][rr + r0 + g + 8][1] = l[1];
    }
}

// ---------------------------------------------------------------------------
// Kernel 3: merge the 2 KV-splits. 4 rows per block, 64 threads per row.
// ---------------------------------------------------------------------------
__global__ __launch_bounds__(256) void combine_kernel(float* __restrict__ out)
{
    int row = blockIdx.x * 4 + (threadIdx.x >> 6);
    int c = threadIdx.x & 63;
    float m0 = g_ml[0][row][0], l0 = g_ml[0][row][1];
    float m1 = g_ml[1][row][0], l1 = g_ml[1][row][1];
    float M = fmaxf(m0, m1);
    float e0 = __expf(m0 - M), e1 = __expf(m1 - M);
    float L = e0 * l0 + e1 * l1;
    size_t idx = (size_t)row * NH + c;
    out[idx] = (e0 * g_Op[0][idx] + e1 * g_Op[1][idx]) / L;
}

// ---------------------------------------------------------------------------
extern "C" void kernel_launch(void* const* d_in, const int* in_sizes, int n_in,
                              void* d_out, int out_size)
{
    const float* x  = (const float*)d_in[0];
    const float* wq = (const float*)d_in[1];
    const float* wk = (const float*)d_in[2];
    const float* wv = (const float*)d_in[3];
    float* out = (float*)d_out;
    (void)in_sizes; (void)n_in; (void)out_size;

    qkv_kernel<<<(NB * NT) / 64, 256>>>(x, wq, wk, wv);
    attn_kernel<<<dim3(NT / 64, NB, SPLIT), 128>>>();
    combine_kernel<<<(NB * NT) / 4, 256>>>(out);
}